// round 6
// baseline (speedup 1.0000x reference)
#include <cuda_runtime.h>
#include <cuda_bf16.h>
#include <math.h>
#include <stdint.h>

#define SS 2048
#define DD 2048
#define HH 16
#define EE 128
#define NQKV (3*EE)        // 384
#define NTOT (HH*NQKV)     // 6144
// 1/sqrt(128) * log2(e): scores come out in log2-domain -> exp2f softmax
#define SCALE_E2 (0.08838834764831845f * 1.4426950408889634f)

// ---------------------------------------------------------------------------
// Device scratch (static — no runtime allocation allowed)
// ---------------------------------------------------------------------------
__device__ __nv_bfloat16 g_xhi[(size_t)SS * DD];
__device__ __nv_bfloat16 g_xlo[(size_t)SS * DD];
__device__ __nv_bfloat16 g_wthi[(size_t)NTOT * DD];
__device__ __nv_bfloat16 g_wtlo[(size_t)NTOT * DD];
// Projected Q/K/V, split bf16, layout [h][s][e]  (Q pre-scaled by log2e/sqrt(E))
__device__ __nv_bfloat16 g_qhi[(size_t)HH * SS * EE];
__device__ __nv_bfloat16 g_qlo[(size_t)HH * SS * EE];
__device__ __nv_bfloat16 g_khi[(size_t)HH * SS * EE];
__device__ __nv_bfloat16 g_klo[(size_t)HH * SS * EE];
__device__ __nv_bfloat16 g_vhi[(size_t)HH * SS * EE];
__device__ __nv_bfloat16 g_vlo[(size_t)HH * SS * EE];

// ---------------------------------------------------------------------------
// PTX helpers (base-target-safe)
// ---------------------------------------------------------------------------
__device__ __forceinline__ uint32_t smem_u32(const void* p) {
  uint32_t a;
  asm("{ .reg .u64 t; cvta.to.shared.u64 t, %1; cvt.u32.u64 %0, t; }"
      : "=r"(a) : "l"(p));
  return a;
}

#define LDSM_X4(r, a)                                                        \
  asm volatile("ldmatrix.sync.aligned.m8n8.x4.shared.b16 {%0,%1,%2,%3}, [%4];" \
               : "=r"((r)[0]), "=r"((r)[1]), "=r"((r)[2]), "=r"((r)[3])      \
               : "r"(a))

#define LDSM_X4_T(r, a)                                                      \
  asm volatile("ldmatrix.sync.aligned.m8n8.x4.trans.shared.b16 {%0,%1,%2,%3}, [%4];" \
               : "=r"((r)[0]), "=r"((r)[1]), "=r"((r)[2]), "=r"((r)[3])      \
               : "r"(a))

__device__ __forceinline__ void mma16816(float* c, const uint32_t* a,
                                         const uint32_t* b) {
  asm volatile(
      "mma.sync.aligned.m16n8k16.row.col.f32.bf16.bf16.f32 "
      "{%0,%1,%2,%3}, {%4,%5,%6,%7}, {%8,%9}, {%0,%1,%2,%3};"
      : "+f"(c[0]), "+f"(c[1]), "+f"(c[2]), "+f"(c[3])
      : "r"(a[0]), "r"(a[1]), "r"(a[2]), "r"(a[3]), "r"(b[0]), "r"(b[1]));
}

#define CP16(sm, gp)                                                   \
  asm volatile("cp.async.cg.shared.global [%0], [%1], 16;" ::          \
               "r"(sm), "l"(gp))
#define CP_COMMIT() asm volatile("cp.async.commit_group;" ::: "memory")
#define CP_WAIT(n)  asm volatile("cp.async.wait_group %0;" :: "n"(n) : "memory")

__device__ __forceinline__ void splitf(float v, float& hf, float& lf) {
  __nv_bfloat16 h = __float2bfloat16(v);
  hf = __bfloat162float(h);
  lf = v - hf;
}
__device__ __forceinline__ uint32_t pack2(float a, float b) {
  __nv_bfloat162 t = __floats2bfloat162_rn(a, b);
  return *(uint32_t*)&t;
}

// ---------------------------------------------------------------------------
// Prep kernel 1: X fp32 -> (hi, lo) bf16 pair
// ---------------------------------------------------------------------------
__global__ __launch_bounds__(256) void convx_kernel(const float* __restrict__ X) {
  size_t i = (size_t)blockIdx.x * blockDim.x + threadIdx.x;
  float4 v = ((const float4*)X)[i];
  __nv_bfloat16 h0 = __float2bfloat16(v.x), h1 = __float2bfloat16(v.y);
  __nv_bfloat16 h2 = __float2bfloat16(v.z), h3 = __float2bfloat16(v.w);
  __nv_bfloat162* hip = (__nv_bfloat162*)g_xhi;
  __nv_bfloat162* lop = (__nv_bfloat162*)g_xlo;
  hip[2*i]   = __nv_bfloat162(h0, h1);
  hip[2*i+1] = __nv_bfloat162(h2, h3);
  lop[2*i]   = __nv_bfloat162(__float2bfloat16(v.x - __bfloat162float(h0)),
                              __float2bfloat16(v.y - __bfloat162float(h1)));
  lop[2*i+1] = __nv_bfloat162(__float2bfloat16(v.z - __bfloat162float(h2)),
                              __float2bfloat16(v.w - __bfloat162float(h3)));
}

// ---------------------------------------------------------------------------
// Prep kernel 2: W[h][d][j] -> Wt[n=h*384+j][d] as (hi, lo) bf16
// ---------------------------------------------------------------------------
__global__ __launch_bounds__(256) void convw_kernel(const float* __restrict__ W) {
  __shared__ float t[32][33];
  int h = blockIdx.z;
  int j0 = blockIdx.x * 32, d0 = blockIdx.y * 32;
  int tx = threadIdx.x & 31, ty = threadIdx.x >> 5;
  const float* Wh = W + (size_t)h * DD * NQKV;
  #pragma unroll
  for (int i = 0; i < 4; i++) {
    int d = d0 + ty + i * 8;
    t[ty + i * 8][tx] = Wh[(size_t)d * NQKV + j0 + tx];
  }
  __syncthreads();
  #pragma unroll
  for (int i = 0; i < 4; i++) {
    int j = j0 + ty + i * 8;
    float v = t[tx][ty + i * 8];
    size_t o = (size_t)(h * NQKV + j) * DD + d0 + tx;
    __nv_bfloat16 hi = __float2bfloat16(v);
    g_wthi[o] = hi;
    g_wtlo[o] = __float2bfloat16(v - __bfloat162float(hi));
  }
}

// ---------------------------------------------------------------------------
// QKV GEMM via mma.sync (bf16x3). 512 threads, BM=256, BN=128, BK=32.
// ---------------------------------------------------------------------------
#define BM 256
#define BN 128
#define BK 32
#define NSTAGE_K (DD / BK)          // 64

#define ROWB 80                     // 64B data + 16B pad
#define TILE_A (BM * ROWB)          // 20480
#define TILE_B (BN * ROWB)          // 10240
#define STAGEB (2 * TILE_A + 2 * TILE_B)   // 61440
#define GEMM_SMEM (2 * STAGEB)             // 122880

__global__ __launch_bounds__(512, 1) void qkv_mma_kernel() {
  extern __shared__ char smem[];
  const uint32_t sb = smem_u32(smem);
  const int tid = threadIdx.x;
  const int lane = tid & 31;
  const int wid = tid >> 5;
  const int warp_m = wid >> 2;           // 0..3
  const int warp_n = wid & 3;            // 0..3
  const int m0 = blockIdx.y * BM;
  const int n0 = blockIdx.x * BN;

  float acc[4][4][4];
  #pragma unroll
  for (int i = 0; i < 4; i++)
    #pragma unroll
    for (int j = 0; j < 4; j++)
      #pragma unroll
      for (int q = 0; q < 4; q++) acc[i][j][q] = 0.f;

  const uint32_t a_lrow = (uint32_t)(lane & 15);
  const uint32_t a_lcol = (uint32_t)((lane >> 4) * 16);
  const uint32_t b_lrow = (uint32_t)((lane & 7) + ((lane >> 4) << 3));
  const uint32_t b_lcol = (uint32_t)(((lane >> 3) & 1) * 16);

  auto load_stage = [&](int buf, int c) {
    const int k0 = c * BK;
    const uint32_t sbase = sb + buf * STAGEB;
    #pragma unroll
    for (int i = 0; i < 2; i++) {
      int idx = tid + i * 512;
      int r = idx >> 2, cc = idx & 3;
      uint32_t so = sbase + (uint32_t)(r * ROWB + cc * 16);
      size_t goA = (size_t)(m0 + r) * DD + k0 + cc * 8;
      CP16(so,          g_xhi + goA);
      CP16(so + TILE_A, g_xlo + goA);
    }
    {
      int r = tid >> 2, cc = tid & 3;
      uint32_t so = sbase + 2 * TILE_A + (uint32_t)(r * ROWB + cc * 16);
      size_t goB = (size_t)(n0 + r) * DD + k0 + cc * 8;
      CP16(so,          g_wthi + goB);
      CP16(so + TILE_B, g_wtlo + goB);
    }
  };

  load_stage(0, 0);
  CP_COMMIT();

  for (int c = 0; c < NSTAGE_K; c++) {
    CP_WAIT(0);
    __syncthreads();
    if (c + 1 < NSTAGE_K) {
      load_stage((c + 1) & 1, c + 1);
      CP_COMMIT();
    }

    const uint32_t sbase = sb + (c & 1) * STAGEB;
    const uint32_t sAh = sbase;
    const uint32_t sAl = sbase + TILE_A;
    const uint32_t sBh = sbase + 2 * TILE_A;
    const uint32_t sBl = sbase + 2 * TILE_A + TILE_B;

    #pragma unroll
    for (int ks = 0; ks < 2; ks++) {
      const uint32_t kb = (uint32_t)(ks * 32);
      uint32_t ah[4][4], al[4][4];
      #pragma unroll
      for (int mt = 0; mt < 4; mt++) {
        uint32_t row0 = (uint32_t)(warp_m * 64 + mt * 16);
        uint32_t off = (row0 + a_lrow) * ROWB + kb + a_lcol;
        LDSM_X4(ah[mt], sAh + off);
        LDSM_X4(al[mt], sAl + off);
      }
      uint32_t bh[4][2], bl[4][2];
      #pragma unroll
      for (int np = 0; np < 2; np++) {
        uint32_t nrow0 = (uint32_t)(warp_n * 32 + np * 16);
        uint32_t off = (nrow0 + b_lrow) * ROWB + kb + b_lcol;
        uint32_t q[4];
        LDSM_X4(q, sBh + off);
        bh[2*np][0] = q[0]; bh[2*np][1] = q[1];
        bh[2*np+1][0] = q[2]; bh[2*np+1][1] = q[3];
        LDSM_X4(q, sBl + off);
        bl[2*np][0] = q[0]; bl[2*np][1] = q[1];
        bl[2*np+1][0] = q[2]; bl[2*np+1][1] = q[3];
      }
      #pragma unroll
      for (int mt = 0; mt < 4; mt++) {
        #pragma unroll
        for (int nt = 0; nt < 4; nt++) {
          mma16816(acc[mt][nt], ah[mt], bh[nt]);
          mma16816(acc[mt][nt], ah[mt], bl[nt]);
          mma16816(acc[mt][nt], al[mt], bh[nt]);
        }
      }
    }
    __syncthreads();
  }

  // Epilogue: write split-bf16 into g_{q,k,v}{hi,lo}[h][s][e]
  const int g = lane >> 2, tig = lane & 3;
  const int h    = n0 / NQKV;
  const int part = (n0 % NQKV) / EE;           // 0=Q 1=K 2=V
  __nv_bfloat16* dhi = (part == 0) ? g_qhi : (part == 1) ? g_khi : g_vhi;
  __nv_bfloat16* dlo = (part == 0) ? g_qlo : (part == 1) ? g_klo : g_vlo;
  const float scl = (part == 0) ? SCALE_E2 : 1.0f;

  #pragma unroll
  for (int mt = 0; mt < 4; mt++) {
    int row = m0 + warp_m * 64 + mt * 16 + g;
    #pragma unroll
    for (int nt = 0; nt < 4; nt++) {
      int col = warp_n * 32 + nt * 8 + tig * 2;
      #pragma unroll
      for (int half = 0; half < 2; half++) {
        int r = row + half * 8;
        float v0 = acc[mt][nt][2*half]     * scl;
        float v1 = acc[mt][nt][2*half + 1] * scl;
        float h0, l0, h1, l1;
        splitf(v0, h0, l0);
        splitf(v1, h1, l1);
        size_t base = ((size_t)h * SS + r) * EE + col;
        *(uint32_t*)&dhi[base] = pack2(h0, h1);
        *(uint32_t*)&dlo[base] = pack2(l0, l1);
      }
    }
  }
}

// ---------------------------------------------------------------------------
// Flash attention, software-pipelined: S_{t+1} MMAs overlap softmax_t.
// 128 q-rows x head, 8 warps, KV tiles of 32, 3-stage cp.async ring.
// ---------------------------------------------------------------------------
#define AQ  128
#define AKV 32
#define NKV (SS / AKV)        // 64
#define AROWB 272             // 256B data + 16B pad

#define SQH 0
#define SQL (AQ * AROWB)                  // 34816
#define SST (2 * AQ * AROWB)              // 69632
#define KVT (AKV * AROWB)                 // 8704
#define STAGE (4 * KVT)                   // 34816  (Kh,Kl,Vh,Vl)
#define ATT_SMEM (SST + 3 * STAGE)        // 174080

__global__ __launch_bounds__(256, 1) void attn_mma_kernel(float* __restrict__ out) {
  extern __shared__ char smem[];
  const uint32_t sb = smem_u32(smem);
  const int tid  = threadIdx.x;
  const int lane = tid & 31;
  const int warp = tid >> 5;
  const int h  = blockIdx.y;
  const int q0 = blockIdx.x * AQ;

  const __nv_bfloat16* qh = g_qhi + ((size_t)h * SS + q0) * EE;
  const __nv_bfloat16* ql = g_qlo + ((size_t)h * SS + q0) * EE;
  const __nv_bfloat16* kh = g_khi + (size_t)h * SS * EE;
  const __nv_bfloat16* kl = g_klo + (size_t)h * SS * EE;
  const __nv_bfloat16* vh = g_vhi + (size_t)h * SS * EE;
  const __nv_bfloat16* vl = g_vlo + (size_t)h * SS * EE;

  // Q tile -> smem
  #pragma unroll
  for (int i = 0; i < 8; i++) {
    int idx = tid + i * 256;
    int r = idx >> 4, cc = idx & 15;
    uint32_t so = (uint32_t)(r * AROWB + cc * 16);
    *(uint4*)(smem + SQH + so) = *(const uint4*)(qh + (size_t)r * EE + cc * 8);
    *(uint4*)(smem + SQL + so) = *(const uint4*)(ql + (size_t)r * EE + cc * 8);
  }

  auto load_kv = [&](int buf, int t) {
    const int kv0 = t * AKV;
    const uint32_t sbase = sb + SST + buf * STAGE;
    #pragma unroll
    for (int i = 0; i < 2; i++) {
      int idx = tid + i * 256;            // 0..511
      int r = idx >> 4, cc = idx & 15;
      uint32_t so = sbase + (uint32_t)(r * AROWB + cc * 16);
      size_t go = (size_t)(kv0 + r) * EE + cc * 8;
      CP16(so,           kh + go);
      CP16(so + KVT,     kl + go);
      CP16(so + 2*KVT,   vh + go);
      CP16(so + 3*KVT,   vl + go);
    }
  };

  load_kv(0, 0); CP_COMMIT();
  load_kv(1, 1); CP_COMMIT();

  const int g   = lane >> 2;
  const int tig = lane & 3;
  const uint32_t a_lrow = (uint32_t)(lane & 15);
  const uint32_t a_lcol = (uint32_t)((lane >> 4) * 16);
  const uint32_t b_lrow = (uint32_t)((lane & 7) + ((lane >> 4) << 3));
  const uint32_t b_lcol = (uint32_t)(((lane >> 3) & 1) * 16);
  const uint32_t v_row  = (uint32_t)((lane & 7) + (((lane >> 3) & 1) << 3));
  const uint32_t v_colb = (uint32_t)(((lane >> 4) * 8) * 2);

  float m0 = -INFINITY, m1 = -INFINITY, l0 = 0.f, l1 = 0.f;
  float oacc[16][4];
  #pragma unroll
  for (int i = 0; i < 16; i++)
    #pragma unroll
    for (int j = 0; j < 4; j++) oacc[i][j] = 0.f;

  // S = Q K^T for one 32-wide KV tile (bf16x3 split): sacc[4][4]
  auto computeS = [&](uint32_t sK, float (&sacc)[4][4]) {
    #pragma unroll
    for (int i = 0; i < 4; i++)
      #pragma unroll
      for (int j = 0; j < 4; j++) sacc[i][j] = 0.f;
    #pragma unroll
    for (int ks = 0; ks < 8; ks++) {
      const uint32_t kb = (uint32_t)(ks * 32);
      uint32_t ah[4], al[4];
      uint32_t qoff = (uint32_t)(warp * 16 + a_lrow) * AROWB + kb + a_lcol;
      LDSM_X4(ah, sb + SQH + qoff);
      LDSM_X4(al, sb + SQL + qoff);
      #pragma unroll
      for (int np = 0; np < 2; np++) {
        uint32_t koff = (uint32_t)(np * 16 + b_lrow) * AROWB + kb + b_lcol;
        uint32_t h4[4], l4[4];
        LDSM_X4(h4, sK  + koff);
        LDSM_X4(l4, sK + KVT + koff);
        uint32_t bh0[2] = {h4[0], h4[1]}, bh1[2] = {h4[2], h4[3]};
        uint32_t bl0[2] = {l4[0], l4[1]}, bl1[2] = {l4[2], l4[3]};
        mma16816(sacc[2*np],   ah, bh0);
        mma16816(sacc[2*np],   ah, bl0);
        mma16816(sacc[2*np],   al, bh0);
        mma16816(sacc[2*np+1], ah, bh1);
        mma16816(sacc[2*np+1], ah, bl1);
        mma16816(sacc[2*np+1], al, bh1);
      }
    }
  };

  // one pipeline step: prefetch t+2, compute S_{t+1} (into nxt) overlapped
  // with softmax(cur), then O += P*V_t
  auto step = [&](int t, float (&cur)[4][4], float (&nxt)[4][4]) {
    const uint32_t sVt = sb + SST + (uint32_t)((t % 3) * STAGE) + 2 * KVT;

    if (t + 1 < NKV) {
      CP_WAIT(0);
      __syncthreads();
      if (t + 2 < NKV) {
        load_kv((t + 2) % 3, t + 2);
        CP_COMMIT();
      }
      // independent of softmax(cur) below — scheduler interleaves
      computeS(sb + SST + (uint32_t)(((t + 1) % 3) * STAGE), nxt);
    }

    // ---- softmax on cur (log2 domain) ----
    float r0 = -INFINITY, r1 = -INFINITY;
    #pragma unroll
    for (int i = 0; i < 4; i++) {
      r0 = fmaxf(r0, fmaxf(cur[i][0], cur[i][1]));
      r1 = fmaxf(r1, fmaxf(cur[i][2], cur[i][3]));
    }
    r0 = fmaxf(r0, __shfl_xor_sync(0xffffffffu, r0, 1));
    r0 = fmaxf(r0, __shfl_xor_sync(0xffffffffu, r0, 2));
    r1 = fmaxf(r1, __shfl_xor_sync(0xffffffffu, r1, 1));
    r1 = fmaxf(r1, __shfl_xor_sync(0xffffffffu, r1, 2));

    float mn0 = fmaxf(m0, r0), mn1 = fmaxf(m1, r1);
    float al0 = exp2f(m0 - mn0), al1 = exp2f(m1 - mn1);
    m0 = mn0; m1 = mn1;

    float ps0 = 0.f, ps1 = 0.f;
    #pragma unroll
    for (int i = 0; i < 4; i++) {
      cur[i][0] = exp2f(cur[i][0] - mn0);
      cur[i][1] = exp2f(cur[i][1] - mn0);
      cur[i][2] = exp2f(cur[i][2] - mn1);
      cur[i][3] = exp2f(cur[i][3] - mn1);
      ps0 += cur[i][0] + cur[i][1];
      ps1 += cur[i][2] + cur[i][3];
    }
    ps0 += __shfl_xor_sync(0xffffffffu, ps0, 1);
    ps0 += __shfl_xor_sync(0xffffffffu, ps0, 2);
    ps1 += __shfl_xor_sync(0xffffffffu, ps1, 1);
    ps1 += __shfl_xor_sync(0xffffffffu, ps1, 2);
    l0 = l0 * al0 + ps0;
    l1 = l1 * al1 + ps1;

    #pragma unroll
    for (int i = 0; i < 16; i++) {
      oacc[i][0] *= al0; oacc[i][1] *= al0;
      oacc[i][2] *= al1; oacc[i][3] *= al1;
    }

    // ---- O += P V_t (bf16x3 split) ----
    #pragma unroll
    for (int j = 0; j < 2; j++) {
      float h00, q00, h01, q01, h02, q02, h03, q03;
      float h10, q10, h11, q11, h12, q12, h13, q13;
      splitf(cur[2*j][0],   h00, q00); splitf(cur[2*j][1],   h01, q01);
      splitf(cur[2*j][2],   h02, q02); splitf(cur[2*j][3],   h03, q03);
      splitf(cur[2*j+1][0], h10, q10); splitf(cur[2*j+1][1], h11, q11);
      splitf(cur[2*j+1][2], h12, q12); splitf(cur[2*j+1][3], h13, q13);
      uint32_t ph[4], pl[4];
      ph[0] = pack2(h00, h01); ph[1] = pack2(h02, h03);
      ph[2] = pack2(h10, h11); ph[3] = pack2(h12, h13);
      pl[0] = pack2(q00, q01); pl[1] = pack2(q02, q03);
      pl[2] = pack2(q10, q11); pl[3] = pack2(q12, q13);

      #pragma unroll
      for (int ep = 0; ep < 8; ep++) {
        uint32_t voff = (uint32_t)(j * 16 + v_row) * AROWB + (uint32_t)(ep * 32) + v_colb;
        uint32_t h4[4], l4[4];
        LDSM_X4_T(h4, sVt + voff);
        LDSM_X4_T(l4, sVt + KVT + voff);
        uint32_t bh0[2] = {h4[0], h4[1]}, bh1[2] = {h4[2], h4[3]};
        uint32_t bl0[2] = {l4[0], l4[1]}, bl1[2] = {l4[2], l4[3]};
        mma16816(oacc[2*ep],   ph, bh0);
        mma16816(oacc[2*ep],   ph, bl0);
        mma16816(oacc[2*ep],   pl, bh0);
        mma16816(oacc[2*ep+1], ph, bh1);
        mma16816(oacc[2*ep+1], ph, bl1);
        mma16816(oacc[2*ep+1], pl, bh1);
      }
    }
  };

  // prologue: S_0
  float sA[4][4], sB[4][4];
  CP_WAIT(1);                 // tile 0 resident (tile 1 may still fly)
  __syncthreads();            // Q stores + tile 0 visible
  computeS(sb + SST, sA);

  for (int t = 0; t < NKV; t += 2) {
    step(t,     sA, sB);
    step(t + 1, sB, sA);
  }

  // ---- normalize + write ----
  const float i0 = 1.f / l0, i1 = 1.f / l1;
  const int row0 = q0 + warp * 16 + g;
  #pragma unroll
  for (int et = 0; et < 16; et++) {
    int col = h * EE + et * 8 + tig * 2;
    *(float2*)&out[(size_t)row0 * (HH*EE) + col] =
        make_float2(oacc[et][0] * i0, oacc[et][1] * i0);
    *(float2*)&out[(size_t)(row0 + 8) * (HH*EE) + col] =
        make_float2(oacc[et][2] * i1, oacc[et][3] * i1);
  }
}

// ---------------------------------------------------------------------------
extern "C" void kernel_launch(void* const* d_in, const int* in_sizes, int n_in,
                              void* d_out, int out_size) {
  const float* x = (const float*)d_in[0];     // [2048, 2048]
  const float* w = (const float*)d_in[1];     // [16, 2048, 384]
  float* out = (float*)d_out;                 // [2048, 2048]
  (void)in_sizes; (void)n_in; (void)out_size;

  cudaFuncSetAttribute(qkv_mma_kernel,
                       cudaFuncAttributeMaxDynamicSharedMemorySize, GEMM_SMEM);
  cudaFuncSetAttribute(attn_mma_kernel,
                       cudaFuncAttributeMaxDynamicSharedMemorySize, ATT_SMEM);

  convx_kernel<<<(SS * DD / 4) / 256, 256>>>(x);
  convw_kernel<<<dim3(NQKV / 32, DD / 32, HH), 256>>>(w);

  qkv_mma_kernel<<<dim3(NTOT / BN, SS / BM), 512, GEMM_SMEM>>>();

  attn_mma_kernel<<<dim3(SS / AQ, HH), 256, ATT_SMEM>>>(out);
}

// round 7
// speedup vs baseline: 1.0226x; 1.0226x over previous
#include <cuda_runtime.h>
#include <cuda_bf16.h>
#include <math.h>
#include <stdint.h>

#define SS 2048
#define DD 2048
#define HH 16
#define EE 128
#define NQKV (3*EE)        // 384
#define NTOT (HH*NQKV)     // 6144
// 1/sqrt(128) * log2(e): scores in log2-domain -> exp2f softmax
#define SCALE_E2 (0.08838834764831845f * 1.4426950408889634f)

// ---------------------------------------------------------------------------
// Device scratch (static — no runtime allocation allowed)
// ---------------------------------------------------------------------------
__device__ __nv_bfloat16 g_xhi[(size_t)SS * DD];
__device__ __nv_bfloat16 g_xlo[(size_t)SS * DD];
__device__ __nv_bfloat16 g_wthi[(size_t)NTOT * DD];
__device__ __nv_bfloat16 g_wtlo[(size_t)NTOT * DD];
__device__ __nv_bfloat16 g_qhi[(size_t)HH * SS * EE];
__device__ __nv_bfloat16 g_qlo[(size_t)HH * SS * EE];
__device__ __nv_bfloat16 g_khi[(size_t)HH * SS * EE];
__device__ __nv_bfloat16 g_klo[(size_t)HH * SS * EE];
__device__ __nv_bfloat16 g_vhi[(size_t)HH * SS * EE];
__device__ __nv_bfloat16 g_vlo[(size_t)HH * SS * EE];

// ---------------------------------------------------------------------------
// PTX helpers
// ---------------------------------------------------------------------------
__device__ __forceinline__ uint32_t smem_u32(const void* p) {
  uint32_t a;
  asm("{ .reg .u64 t; cvta.to.shared.u64 t, %1; cvt.u32.u64 %0, t; }"
      : "=r"(a) : "l"(p));
  return a;
}

#define LDSM_X4(r, a)                                                        \
  asm volatile("ldmatrix.sync.aligned.m8n8.x4.shared.b16 {%0,%1,%2,%3}, [%4];" \
               : "=r"((r)[0]), "=r"((r)[1]), "=r"((r)[2]), "=r"((r)[3])      \
               : "r"(a))

#define LDSM_X4_T(r, a)                                                      \
  asm volatile("ldmatrix.sync.aligned.m8n8.x4.trans.shared.b16 {%0,%1,%2,%3}, [%4];" \
               : "=r"((r)[0]), "=r"((r)[1]), "=r"((r)[2]), "=r"((r)[3])      \
               : "r"(a))

__device__ __forceinline__ void mma16816(float* c, const uint32_t* a,
                                         const uint32_t* b) {
  asm volatile(
      "mma.sync.aligned.m16n8k16.row.col.f32.bf16.bf16.f32 "
      "{%0,%1,%2,%3}, {%4,%5,%6,%7}, {%8,%9}, {%0,%1,%2,%3};"
      : "+f"(c[0]), "+f"(c[1]), "+f"(c[2]), "+f"(c[3])
      : "r"(a[0]), "r"(a[1]), "r"(a[2]), "r"(a[3]), "r"(b[0]), "r"(b[1]));
}

#define CP16(sm, gp)                                                   \
  asm volatile("cp.async.cg.shared.global [%0], [%1], 16;" ::          \
               "r"(sm), "l"(gp))
#define CP_COMMIT() asm volatile("cp.async.commit_group;" ::: "memory")
#define CP_WAIT(n)  asm volatile("cp.async.wait_group %0;" :: "n"(n) : "memory")

__device__ __forceinline__ void splitf(float v, float& hf, float& lf) {
  __nv_bfloat16 h = __float2bfloat16(v);
  hf = __bfloat162float(h);
  lf = v - hf;
}
__device__ __forceinline__ uint32_t pack2(float a, float b) {
  __nv_bfloat162 t = __floats2bfloat162_rn(a, b);
  return *(uint32_t*)&t;
}

// ---------------------------------------------------------------------------
// Prep kernel 1: X fp32 -> (hi, lo) bf16 pair
// ---------------------------------------------------------------------------
__global__ __launch_bounds__(256) void convx_kernel(const float* __restrict__ X) {
  size_t i = (size_t)blockIdx.x * blockDim.x + threadIdx.x;
  float4 v = ((const float4*)X)[i];
  __nv_bfloat16 h0 = __float2bfloat16(v.x), h1 = __float2bfloat16(v.y);
  __nv_bfloat16 h2 = __float2bfloat16(v.z), h3 = __float2bfloat16(v.w);
  __nv_bfloat162* hip = (__nv_bfloat162*)g_xhi;
  __nv_bfloat162* lop = (__nv_bfloat162*)g_xlo;
  hip[2*i]   = __nv_bfloat162(h0, h1);
  hip[2*i+1] = __nv_bfloat162(h2, h3);
  lop[2*i]   = __nv_bfloat162(__float2bfloat16(v.x - __bfloat162float(h0)),
                              __float2bfloat16(v.y - __bfloat162float(h1)));
  lop[2*i+1] = __nv_bfloat162(__float2bfloat16(v.z - __bfloat162float(h2)),
                              __float2bfloat16(v.w - __bfloat162float(h3)));
}

// ---------------------------------------------------------------------------
// Prep kernel 2: W[h][d][j] -> Wt[n=h*384+j][d] as (hi, lo) bf16
// ---------------------------------------------------------------------------
__global__ __launch_bounds__(256) void convw_kernel(const float* __restrict__ W) {
  __shared__ float t[32][33];
  int h = blockIdx.z;
  int j0 = blockIdx.x * 32, d0 = blockIdx.y * 32;
  int tx = threadIdx.x & 31, ty = threadIdx.x >> 5;
  const float* Wh = W + (size_t)h * DD * NQKV;
  #pragma unroll
  for (int i = 0; i < 4; i++) {
    int d = d0 + ty + i * 8;
    t[ty + i * 8][tx] = Wh[(size_t)d * NQKV + j0 + tx];
  }
  __syncthreads();
  #pragma unroll
  for (int i = 0; i < 4; i++) {
    int j = j0 + ty + i * 8;
    float v = t[tx][ty + i * 8];
    size_t o = (size_t)(h * NQKV + j) * DD + d0 + tx;
    __nv_bfloat16 hi = __float2bfloat16(v);
    g_wthi[o] = hi;
    g_wtlo[o] = __float2bfloat16(v - __bfloat162float(hi));
  }
}

// ---------------------------------------------------------------------------
// QKV GEMM via mma.sync (bf16x3), term-major MMA ordering.
// 512 threads, BM=256, BN=128, BK=32.
// ---------------------------------------------------------------------------
#define BM 256
#define BN 128
#define BK 32
#define NSTAGE_K (DD / BK)          // 64

#define ROWB 80
#define TILE_A (BM * ROWB)          // 20480
#define TILE_B (BN * ROWB)          // 10240
#define STAGEB (2 * TILE_A + 2 * TILE_B)   // 61440
#define GEMM_SMEM (2 * STAGEB)             // 122880

__global__ __launch_bounds__(512, 1) void qkv_mma_kernel() {
  extern __shared__ char smem[];
  const uint32_t sb = smem_u32(smem);
  const int tid = threadIdx.x;
  const int lane = tid & 31;
  const int wid = tid >> 5;
  const int warp_m = wid >> 2;
  const int warp_n = wid & 3;
  const int m0 = blockIdx.y * BM;
  const int n0 = blockIdx.x * BN;

  float acc[4][4][4];
  #pragma unroll
  for (int i = 0; i < 4; i++)
    #pragma unroll
    for (int j = 0; j < 4; j++)
      #pragma unroll
      for (int q = 0; q < 4; q++) acc[i][j][q] = 0.f;

  const uint32_t a_lrow = (uint32_t)(lane & 15);
  const uint32_t a_lcol = (uint32_t)((lane >> 4) * 16);
  const uint32_t b_lrow = (uint32_t)((lane & 7) + ((lane >> 4) << 3));
  const uint32_t b_lcol = (uint32_t)(((lane >> 3) & 1) * 16);

  auto load_stage = [&](int buf, int c) {
    const int k0 = c * BK;
    const uint32_t sbase = sb + buf * STAGEB;
    #pragma unroll
    for (int i = 0; i < 2; i++) {
      int idx = tid + i * 512;
      int r = idx >> 2, cc = idx & 3;
      uint32_t so = sbase + (uint32_t)(r * ROWB + cc * 16);
      size_t goA = (size_t)(m0 + r) * DD + k0 + cc * 8;
      CP16(so,          g_xhi + goA);
      CP16(so + TILE_A, g_xlo + goA);
    }
    {
      int r = tid >> 2, cc = tid & 3;
      uint32_t so = sbase + 2 * TILE_A + (uint32_t)(r * ROWB + cc * 16);
      size_t goB = (size_t)(n0 + r) * DD + k0 + cc * 8;
      CP16(so,          g_wthi + goB);
      CP16(so + TILE_B, g_wtlo + goB);
    }
  };

  load_stage(0, 0);
  CP_COMMIT();

  for (int c = 0; c < NSTAGE_K; c++) {
    CP_WAIT(0);
    __syncthreads();
    if (c + 1 < NSTAGE_K) {
      load_stage((c + 1) & 1, c + 1);
      CP_COMMIT();
    }

    const uint32_t sbase = sb + (c & 1) * STAGEB;
    const uint32_t sAh = sbase;
    const uint32_t sAl = sbase + TILE_A;
    const uint32_t sBh = sbase + 2 * TILE_A;
    const uint32_t sBl = sbase + 2 * TILE_A + TILE_B;

    #pragma unroll
    for (int ks = 0; ks < 2; ks++) {
      const uint32_t kb = (uint32_t)(ks * 32);
      uint32_t ah[4][4], al[4][4];
      #pragma unroll
      for (int mt = 0; mt < 4; mt++) {
        uint32_t row0 = (uint32_t)(warp_m * 64 + mt * 16);
        uint32_t off = (row0 + a_lrow) * ROWB + kb + a_lcol;
        LDSM_X4(ah[mt], sAh + off);
        LDSM_X4(al[mt], sAl + off);
      }
      uint32_t bh[4][2], bl[4][2];
      #pragma unroll
      for (int np = 0; np < 2; np++) {
        uint32_t nrow0 = (uint32_t)(warp_n * 32 + np * 16);
        uint32_t off = (nrow0 + b_lrow) * ROWB + kb + b_lcol;
        uint32_t q[4];
        LDSM_X4(q, sBh + off);
        bh[2*np][0] = q[0]; bh[2*np][1] = q[1];
        bh[2*np+1][0] = q[2]; bh[2*np+1][1] = q[3];
        LDSM_X4(q, sBl + off);
        bl[2*np][0] = q[0]; bl[2*np][1] = q[1];
        bl[2*np+1][0] = q[2]; bl[2*np+1][1] = q[3];
      }
      // term-major: accumulator reuse distance = 16 MMAs
      #pragma unroll
      for (int mt = 0; mt < 4; mt++)
        #pragma unroll
        for (int nt = 0; nt < 4; nt++)
          mma16816(acc[mt][nt], ah[mt], bh[nt]);
      #pragma unroll
      for (int mt = 0; mt < 4; mt++)
        #pragma unroll
        for (int nt = 0; nt < 4; nt++)
          mma16816(acc[mt][nt], ah[mt], bl[nt]);
      #pragma unroll
      for (int mt = 0; mt < 4; mt++)
        #pragma unroll
        for (int nt = 0; nt < 4; nt++)
          mma16816(acc[mt][nt], al[mt], bh[nt]);
    }
    __syncthreads();
  }

  // Epilogue: write split-bf16 into g_{q,k,v}{hi,lo}[h][s][e]
  const int g = lane >> 2, tig = lane & 3;
  const int h    = n0 / NQKV;
  const int part = (n0 % NQKV) / EE;
  __nv_bfloat16* dhi = (part == 0) ? g_qhi : (part == 1) ? g_khi : g_vhi;
  __nv_bfloat16* dlo = (part == 0) ? g_qlo : (part == 1) ? g_klo : g_vlo;
  const float scl = (part == 0) ? SCALE_E2 : 1.0f;

  #pragma unroll
  for (int mt = 0; mt < 4; mt++) {
    int row = m0 + warp_m * 64 + mt * 16 + g;
    #pragma unroll
    for (int nt = 0; nt < 4; nt++) {
      int col = warp_n * 32 + nt * 8 + tig * 2;
      #pragma unroll
      for (int half = 0; half < 2; half++) {
        int r = row + half * 8;
        float v0 = acc[mt][nt][2*half]     * scl;
        float v1 = acc[mt][nt][2*half + 1] * scl;
        float h0, l0, h1, l1;
        splitf(v0, h0, l0);
        splitf(v1, h1, l1);
        size_t base = ((size_t)h * SS + r) * EE + col;
        *(uint32_t*)&dhi[base] = pack2(h0, h1);
        *(uint32_t*)&dlo[base] = pack2(l0, l1);
      }
    }
  }
}

// ---------------------------------------------------------------------------
// Flash attention (R5 structure: AKV=64, 2-stage) with term-major MMA order.
// ---------------------------------------------------------------------------
#define AQ  128
#define AKV 64
#define NKV (SS / AKV)        // 32
#define AROWB 272

#define SQH 0
#define SQL (AQ * AROWB)
#define SST (2 * AQ * AROWB)              // 69632
#define KVT (AKV * AROWB)                 // 17408
#define STAGE (4 * KVT)                   // 69632
#define ATT_SMEM (SST + 2 * STAGE)        // 208896

__global__ __launch_bounds__(256, 1) void attn_mma_kernel(float* __restrict__ out) {
  extern __shared__ char smem[];
  const uint32_t sb = smem_u32(smem);
  const int tid  = threadIdx.x;
  const int lane = tid & 31;
  const int warp = tid >> 5;
  const int h  = blockIdx.y;
  const int q0 = blockIdx.x * AQ;

  const __nv_bfloat16* qh = g_qhi + ((size_t)h * SS + q0) * EE;
  const __nv_bfloat16* ql = g_qlo + ((size_t)h * SS + q0) * EE;
  const __nv_bfloat16* kh = g_khi + (size_t)h * SS * EE;
  const __nv_bfloat16* kl = g_klo + (size_t)h * SS * EE;
  const __nv_bfloat16* vh = g_vhi + (size_t)h * SS * EE;
  const __nv_bfloat16* vl = g_vlo + (size_t)h * SS * EE;

  #pragma unroll
  for (int i = 0; i < 8; i++) {
    int idx = tid + i * 256;
    int r = idx >> 4, cc = idx & 15;
    uint32_t so = (uint32_t)(r * AROWB + cc * 16);
    *(uint4*)(smem + SQH + so) = *(const uint4*)(qh + (size_t)r * EE + cc * 8);
    *(uint4*)(smem + SQL + so) = *(const uint4*)(ql + (size_t)r * EE + cc * 8);
  }

  auto load_kv = [&](int buf, int t) {
    const int kv0 = t * AKV;
    const uint32_t sbase = sb + SST + buf * STAGE;
    #pragma unroll
    for (int i = 0; i < 4; i++) {
      int idx = tid + i * 256;
      int r = idx >> 4, cc = idx & 15;
      uint32_t so = sbase + (uint32_t)(r * AROWB + cc * 16);
      size_t go = (size_t)(kv0 + r) * EE + cc * 8;
      CP16(so,           kh + go);
      CP16(so + KVT,     kl + go);
      CP16(so + 2*KVT,   vh + go);
      CP16(so + 3*KVT,   vl + go);
    }
  };

  load_kv(0, 0);
  CP_COMMIT();

  const int g   = lane >> 2;
  const int tig = lane & 3;
  const uint32_t a_lrow = (uint32_t)(lane & 15);
  const uint32_t a_lcol = (uint32_t)((lane >> 4) * 16);
  const uint32_t b_lrow = (uint32_t)((lane & 7) + ((lane >> 4) << 3));
  const uint32_t b_lcol = (uint32_t)(((lane >> 3) & 1) * 16);
  const uint32_t v_row  = (uint32_t)((lane & 7) + (((lane >> 3) & 1) << 3));
  const uint32_t v_colb = (uint32_t)(((lane >> 4) * 8) * 2);

  float m0 = -INFINITY, m1 = -INFINITY, l0 = 0.f, l1 = 0.f;
  float oacc[16][4];
  #pragma unroll
  for (int i = 0; i < 16; i++)
    #pragma unroll
    for (int j = 0; j < 4; j++) oacc[i][j] = 0.f;

  for (int t = 0; t < NKV; t++) {
    CP_WAIT(0);
    __syncthreads();
    if (t + 1 < NKV) {
      load_kv((t + 1) & 1, t + 1);
      CP_COMMIT();
    }

    const uint32_t sK  = sb + SST + (t & 1) * STAGE;
    const uint32_t sKl = sK + KVT;
    const uint32_t sV  = sK + 2 * KVT;
    const uint32_t sVl = sK + 3 * KVT;

    // ---- S = Q K^T, term-major (acc reuse distance 8) ----
    float sacc[8][4];
    #pragma unroll
    for (int i = 0; i < 8; i++)
      #pragma unroll
      for (int j = 0; j < 4; j++) sacc[i][j] = 0.f;

    #pragma unroll
    for (int ks = 0; ks < 8; ks++) {
      const uint32_t kb = (uint32_t)(ks * 32);
      uint32_t ah[4], al[4];
      uint32_t qoff = (uint32_t)(warp * 16 + a_lrow) * AROWB + kb + a_lcol;
      LDSM_X4(ah, sb + SQH + qoff);
      LDSM_X4(al, sb + SQL + qoff);
      uint32_t kfh[4][4], kfl[4][4];
      #pragma unroll
      for (int np = 0; np < 4; np++) {
        uint32_t koff = (uint32_t)(np * 16 + b_lrow) * AROWB + kb + b_lcol;
        LDSM_X4(kfh[np], sK  + koff);
        LDSM_X4(kfl[np], sKl + koff);
      }
      #pragma unroll
      for (int np = 0; np < 4; np++) {
        mma16816(sacc[2*np],   ah, &kfh[np][0]);
        mma16816(sacc[2*np+1], ah, &kfh[np][2]);
      }
      #pragma unroll
      for (int np = 0; np < 4; np++) {
        mma16816(sacc[2*np],   ah, &kfl[np][0]);
        mma16816(sacc[2*np+1], ah, &kfl[np][2]);
      }
      #pragma unroll
      for (int np = 0; np < 4; np++) {
        mma16816(sacc[2*np],   al, &kfh[np][0]);
        mma16816(sacc[2*np+1], al, &kfh[np][2]);
      }
    }

    // ---- online softmax (log2 domain) ----
    float r0 = -INFINITY, r1 = -INFINITY;
    #pragma unroll
    for (int i = 0; i < 8; i++) {
      r0 = fmaxf(r0, fmaxf(sacc[i][0], sacc[i][1]));
      r1 = fmaxf(r1, fmaxf(sacc[i][2], sacc[i][3]));
    }
    r0 = fmaxf(r0, __shfl_xor_sync(0xffffffffu, r0, 1));
    r0 = fmaxf(r0, __shfl_xor_sync(0xffffffffu, r0, 2));
    r1 = fmaxf(r1, __shfl_xor_sync(0xffffffffu, r1, 1));
    r1 = fmaxf(r1, __shfl_xor_sync(0xffffffffu, r1, 2));

    float mn0 = fmaxf(m0, r0), mn1 = fmaxf(m1, r1);
    float al0 = exp2f(m0 - mn0), al1 = exp2f(m1 - mn1);
    m0 = mn0; m1 = mn1;

    float ps0 = 0.f, ps1 = 0.f;
    #pragma unroll
    for (int i = 0; i < 8; i++) {
      sacc[i][0] = exp2f(sacc[i][0] - mn0);
      sacc[i][1] = exp2f(sacc[i][1] - mn0);
      sacc[i][2] = exp2f(sacc[i][2] - mn1);
      sacc[i][3] = exp2f(sacc[i][3] - mn1);
      ps0 += sacc[i][0] + sacc[i][1];
      ps1 += sacc[i][2] + sacc[i][3];
    }
    ps0 += __shfl_xor_sync(0xffffffffu, ps0, 1);
    ps0 += __shfl_xor_sync(0xffffffffu, ps0, 2);
    ps1 += __shfl_xor_sync(0xffffffffu, ps1, 1);
    ps1 += __shfl_xor_sync(0xffffffffu, ps1, 2);
    l0 = l0 * al0 + ps0;
    l1 = l1 * al1 + ps1;

    #pragma unroll
    for (int i = 0; i < 16; i++) {
      oacc[i][0] *= al0; oacc[i][1] *= al0;
      oacc[i][2] *= al1; oacc[i][3] *= al1;
    }

    // ---- O += P V (term-major within groups of 4 e-tiles) ----
    #pragma unroll
    for (int j = 0; j < 4; j++) {
      float h00, q00, h01, q01, h02, q02, h03, q03;
      float h10, q10, h11, q11, h12, q12, h13, q13;
      splitf(sacc[2*j][0],   h00, q00); splitf(sacc[2*j][1],   h01, q01);
      splitf(sacc[2*j][2],   h02, q02); splitf(sacc[2*j][3],   h03, q03);
      splitf(sacc[2*j+1][0], h10, q10); splitf(sacc[2*j+1][1], h11, q11);
      splitf(sacc[2*j+1][2], h12, q12); splitf(sacc[2*j+1][3], h13, q13);
      uint32_t ph[4], pl[4];
      ph[0] = pack2(h00, h01); ph[1] = pack2(h02, h03);
      ph[2] = pack2(h10, h11); ph[3] = pack2(h12, h13);
      pl[0] = pack2(q00, q01); pl[1] = pack2(q02, q03);
      pl[2] = pack2(q10, q11); pl[3] = pack2(q12, q13);

      #pragma unroll
      for (int grp = 0; grp < 2; grp++) {
        uint32_t vfh[4][4], vfl[4][4];
        #pragma unroll
        for (int e = 0; e < 4; e++) {
          int ep = grp * 4 + e;
          uint32_t voff = (uint32_t)(j * 16 + v_row) * AROWB + (uint32_t)(ep * 32) + v_colb;
          LDSM_X4_T(vfh[e], sV  + voff);
          LDSM_X4_T(vfl[e], sVl + voff);
        }
        #pragma unroll
        for (int e = 0; e < 4; e++) {
          int ep = grp * 4 + e;
          mma16816(oacc[2*ep],   ph, &vfh[e][0]);
          mma16816(oacc[2*ep+1], ph, &vfh[e][2]);
        }
        #pragma unroll
        for (int e = 0; e < 4; e++) {
          int ep = grp * 4 + e;
          mma16816(oacc[2*ep],   ph, &vfl[e][0]);
          mma16816(oacc[2*ep+1], ph, &vfl[e][2]);
        }
        #pragma unroll
        for (int e = 0; e < 4; e++) {
          int ep = grp * 4 + e;
          mma16816(oacc[2*ep],   pl, &vfh[e][0]);
          mma16816(oacc[2*ep+1], pl, &vfh[e][2]);
        }
      }
    }
  }

  // ---- normalize + write ----
  const float i0 = 1.f / l0, i1 = 1.f / l1;
  const int row0 = q0 + warp * 16 + g;
  #pragma unroll
  for (int et = 0; et < 16; et++) {
    int col = h * EE + et * 8 + tig * 2;
    *(float2*)&out[(size_t)row0 * (HH*EE) + col] =
        make_float2(oacc[et][0] * i0, oacc[et][1] * i0);
    *(float2*)&out[(size_t)(row0 + 8) * (HH*EE) + col] =
        make_float2(oacc[et][2] * i1, oacc[et][3] * i1);
  }
}

// ---------------------------------------------------------------------------
extern "C" void kernel_launch(void* const* d_in, const int* in_sizes, int n_in,
                              void* d_out, int out_size) {
  const float* x = (const float*)d_in[0];
  const float* w = (const float*)d_in[1];
  float* out = (float*)d_out;
  (void)in_sizes; (void)n_in; (void)out_size;

  cudaFuncSetAttribute(qkv_mma_kernel,
                       cudaFuncAttributeMaxDynamicSharedMemorySize, GEMM_SMEM);
  cudaFuncSetAttribute(attn_mma_kernel,
                       cudaFuncAttributeMaxDynamicSharedMemorySize, ATT_SMEM);

  convx_kernel<<<(SS * DD / 4) / 256, 256>>>(x);
  convw_kernel<<<dim3(NQKV / 32, DD / 32, HH), 256>>>(w);

  qkv_mma_kernel<<<dim3(NTOT / BN, SS / BM), 512, GEMM_SMEM>>>();

  attn_mma_kernel<<<dim3(SS / AQ, HH), 256, ATT_SMEM>>>(out);
}